// round 10
// baseline (speedup 1.0000x reference)
#include <cuda_runtime.h>
#include <cuda_bf16.h>
#include <cstdint>

// ---------------- problem shapes ----------------
#define NB    8
#define CIN   256
#define LL    1024
#define VV    25
#define PP    3
#define KWIN  9
#define APAD  28

// ---------------- gemm tiling -------------------
// CTA: 512 threads / 16 warps; 2 positions packed (cols = pos*25+v, 50 valid).
// M=768 (warp: 48 rows = 3 mtiles), N=56 (7 ntiles of 8), K=256 (16 ksteps).
#define MT    3
#define NT    7
#define KS    16
#define STR_ST 264              // sT row stride in bf16 elements
#define STR_Y  58               // Y row stride in floats (even: float2-safe; mod32=26)

// smem layout (bytes)
#define SM_STH   0
#define SM_STL   33792          // 64*264*2
#define SM_Y     0              // union with sT (written after GEMM)
#define SM_AEFF  178176         // 768*58*4
#define SM_RED   186576
#define SM_TOTAL 186752

// ---------------- device scratch ----------------
__device__ float         g_s[NB*CIN*LL*VV];          // temporal sliding sums
__device__ __nv_bfloat16 g_Wf[2*48*KS*32*8];         // fragment-major W (hi, lo)
__device__ float         g_Aeff[PP*VV*APAD];         // A_p * ei, padded rows
__device__ float         g_bA[256*VV];               // folded bias

// ---------------------------------------------------------------------------
// prep: pack conv_w into m16n8k16 A-fragment layout (bf16 hi/lo planes);
// build Aeff (padded) and folded bias bA.
// ---------------------------------------------------------------------------
__global__ void prep_kernel(const float* __restrict__ conv_w,
                            const float* __restrict__ A1,
                            const float* __restrict__ A2,
                            const float* __restrict__ A3,
                            const float* __restrict__ ei,
                            const float* __restrict__ conv_b) {
    const int o = blockIdx.x;       // 0..767
    const int k = threadIdx.x;      // 0..255
    {
        float w = conv_w[o*CIN + k];
        __nv_bfloat16 h = __float2bfloat16(w);
        __nv_bfloat16 l = __float2bfloat16(w - __bfloat162float(h));
        const int mt  = o >> 4, r = o & 15;
        const int ks  = k >> 4, kk = k & 15;
        const int reg = ((r >> 3) & 1) | ((kk >> 3) << 1);   // a0..a3
        const int lane = (r & 7) * 4 + ((kk & 7) >> 1);
        const int byt  = kk & 1;
        const size_t off = ((((size_t)mt)*KS + ks)*32 + lane)*8 + reg*2 + byt;
        g_Wf[off] = h;
        g_Wf[(size_t)48*KS*32*8 + off] = l;
    }
    if (blockIdx.x == 0) {
        for (int i = k; i < PP*VV*APAD; i += 256) {
            int p = i/(VV*APAD), rr = i%(VV*APAD), v = rr/APAD, w2 = rr%APAD;
            const float* Ap = (p==0) ? A1 : ((p==1) ? A2 : A3);
            g_Aeff[i] = (w2 < VV) ? Ap[v*VV + w2] * ei[p*VV*VV + v*VV + w2] : 0.f;
        }
    }
    if (blockIdx.x == 1) {
        const int c = k;
        for (int w2 = 0; w2 < VV; ++w2) {
            float acc = 0.f;
            for (int p = 0; p < PP; ++p) {
                const float* Ap = (p==0) ? A1 : ((p==1) ? A2 : A3);
                float cs = 0.f;
                for (int v = 0; v < VV; ++v)
                    cs += Ap[v*VV + w2] * ei[p*VV*VV + v*VV + w2];
                acc += conv_b[p*256 + c] * cs;
            }
            g_bA[c*VV + w2] = acc;
        }
    }
}

// ---------------------------------------------------------------------------
// temporal: causal 9-tap sliding sum over L.
// ---------------------------------------------------------------------------
__global__ void temporal_kernel(const float* __restrict__ x) {
    int t = blockIdx.x * blockDim.x + threadIdx.x;
    if (t >= NB*CIN*VV) return;
    int v  = t % VV;
    int rc = t / VV;
    int base = rc * (LL*VV) + v;
    float run = 0.f;
    #pragma unroll 4
    for (int m = 0; m < LL; ++m) {
        run += x[base + m*VV];
        if (m >= KWIN) run -= x[base + (m - KWIN)*VV];
        g_s[base + m*VV] = run;
    }
}

// ---------------------------------------------------------------------------
__device__ __forceinline__ void mma16816(float c[4], const uint32_t a[4],
                                         const uint32_t b[2]) {
    asm volatile(
        "mma.sync.aligned.m16n8k16.row.col.f32.bf16.bf16.f32 "
        "{%0,%1,%2,%3}, {%4,%5,%6,%7}, {%8,%9}, {%0,%1,%2,%3};"
        : "+f"(c[0]), "+f"(c[1]), "+f"(c[2]), "+f"(c[3])
        : "r"(a[0]), "r"(a[1]), "r"(a[2]), "r"(a[3]), "r"(b[0]), "r"(b[1]));
}

// ---------------------------------------------------------------------------
// fused mma.sync GEMM (bf16 3-pass hi/lo, A-hi register reuse) + spatial + LN.
// One CTA = 2 positions; 512 threads.
// ---------------------------------------------------------------------------
__global__ __launch_bounds__(512, 1)
void gemm_kernel(const float* __restrict__ x,
                 const float* __restrict__ ln_gamma,
                 const float* __restrict__ ln_beta,
                 float* __restrict__ out) {
    extern __shared__ char smem[];
    __nv_bfloat16* sth = (__nv_bfloat16*)(smem + SM_STH);
    __nv_bfloat16* stl = (__nv_bfloat16*)(smem + SM_STL);
    float*         Ysh = (float*)(smem + SM_Y);
    float*         Ae  = (float*)(smem + SM_AEFF);
    float*         red = (float*)(smem + SM_RED);

    const int t = threadIdx.x, wid = t >> 5, lane = t & 31;
    const int n  = blockIdx.x >> 9;
    const int m0 = (blockIdx.x & 511) * 2;

    // Aeff (separate region, persists through epilogue)
    for (int i = t; i < PP*VV*APAD; i += 512) Ae[i] = g_Aeff[i];

    // stage s -> bf16 hi/lo transposed: thread = (ci, pos), 25 contiguous floats
    {
        const int ci = t & 255, posl = t >> 8;
        const float* srow = &g_s[((n*CIN + ci)*LL + (m0 + posl))*VV];
        #pragma unroll
        for (int v = 0; v < VV; ++v) {
            float sv = srow[v];
            __nv_bfloat16 h = __float2bfloat16(sv);
            __nv_bfloat16 l = __float2bfloat16(sv - __bfloat162float(h));
            const int row = posl*VV + v;
            sth[row*STR_ST + ci] = h;
            stl[row*STR_ST + ci] = l;
        }
        // zero pad rows 50..55 (rows 8*6..8*7-1 touched by nt=6)
        const __nv_bfloat16 z = __float2bfloat16(0.f);
        for (int i = t; i < 6*STR_ST; i += 512) {
            sth[50*STR_ST + i] = z;
            stl[50*STR_ST + i] = z;
        }
    }
    __syncthreads();

    // -------------------- GEMM --------------------
    float acc[MT][NT][4];
    #pragma unroll
    for (int mt = 0; mt < MT; ++mt)
        #pragma unroll
        for (int nt = 0; nt < NT; ++nt)
            #pragma unroll
            for (int r = 0; r < 4; ++r) acc[mt][nt][r] = 0.f;

    const uint4* __restrict__ Wf4 = (const uint4*)g_Wf;
    const int mbase = wid * MT;                  // warp's first mtile (0..45)
    const int brow  = (lane >> 2);
    const int bcol  = 2 * (lane & 3);

    uint4 Ah[MT], Al[MT];
    #pragma unroll
    for (int mt = 0; mt < MT; ++mt)
        Ah[mt] = Wf4[((size_t)(mbase + mt)*KS + 0)*32 + lane];

    for (int ks = 0; ks < KS; ++ks) {
        // issue A-lo loads early (consumed in pass 3)
        #pragma unroll
        for (int mt = 0; mt < MT; ++mt)
            Al[mt] = Wf4[((size_t)(48 + mbase + mt)*KS + ks)*32 + lane];

        // ---- pass 1: hh (A hi, B hi) ----
        #pragma unroll
        for (int nt = 0; nt < NT; ++nt) {
            const int o = (nt*8 + brow)*STR_ST + ks*16 + bcol;
            uint32_t b2[2];
            b2[0] = *(const uint32_t*)(sth + o);
            b2[1] = *(const uint32_t*)(sth + o + 8);
            #pragma unroll
            for (int mt = 0; mt < MT; ++mt)
                mma16816(acc[mt][nt], (const uint32_t*)&Ah[mt], b2);
        }
        // ---- pass 2: hl (A hi reused, B lo) ----
        #pragma unroll
        for (int nt = 0; nt < NT; ++nt) {
            const int o = (nt*8 + brow)*STR_ST + ks*16 + bcol;
            uint32_t b2[2];
            b2[0] = *(const uint32_t*)(stl + o);
            b2[1] = *(const uint32_t*)(stl + o + 8);
            #pragma unroll
            for (int mt = 0; mt < MT; ++mt)
                mma16816(acc[mt][nt], (const uint32_t*)&Ah[mt], b2);
        }
        // prefetch next-ks A hi (Ah regs free after hl pass)
        {
            const int ksn = (ks + 1) & (KS - 1);
            #pragma unroll
            for (int mt = 0; mt < MT; ++mt)
                Ah[mt] = Wf4[((size_t)(mbase + mt)*KS + ksn)*32 + lane];
        }
        // ---- pass 3: lh (A lo, B hi) ----
        #pragma unroll
        for (int nt = 0; nt < NT; ++nt) {
            const int o = (nt*8 + brow)*STR_ST + ks*16 + bcol;
            uint32_t b2[2];
            b2[0] = *(const uint32_t*)(sth + o);
            b2[1] = *(const uint32_t*)(sth + o + 8);
            #pragma unroll
            for (int mt = 0; mt < MT; ++mt)
                mma16816(acc[mt][nt], (const uint32_t*)&Al[mt], b2);
        }
    }
    __syncthreads();   // sT dead; Y region reusable

    // -------------------- STS Y --------------------
    #pragma unroll
    for (int mt = 0; mt < MT; ++mt) {
        const int row0 = wid*48 + mt*16 + (lane >> 2);
        #pragma unroll
        for (int nt = 0; nt < NT; ++nt) {
            const int col = nt*8 + 2*(lane & 3);
            *(float2*)&Ysh[row0*STR_Y + col] =
                make_float2(acc[mt][nt][0], acc[mt][nt][1]);
            *(float2*)&Ysh[(row0+8)*STR_Y + col] =
                make_float2(acc[mt][nt][2], acc[mt][nt][3]);
        }
    }
    __syncthreads();

    // ---------- epilogue: spatial + LN + residual (both positions at once) ----
    const int pos = t >> 8;          // warps 0-7 -> pos 0, warps 8-15 -> pos 1
    const int c   = t & 255;
    const int m   = m0 + pos;

    float z[APAD];
    #pragma unroll
    for (int w = 0; w < APAD; ++w) z[w] = 0.f;

    #pragma unroll
    for (int p = 0; p < PP; ++p) {
        const float* yrow = &Ysh[(p*256 + c)*STR_Y + pos*VV];
        const float* arow = Ae + p*VV*APAD;
        #pragma unroll
        for (int v = 0; v < VV; ++v) {
            const float yv = yrow[v];
            const float4* a4 = (const float4*)(arow + v*APAD);
            #pragma unroll
            for (int j = 0; j < 7; ++j) {
                float4 a = a4[j];
                z[4*j+0] = fmaf(yv, a.x, z[4*j+0]);
                z[4*j+1] = fmaf(yv, a.y, z[4*j+1]);
                z[4*j+2] = fmaf(yv, a.z, z[4*j+2]);
                z[4*j+3] = fmaf(yv, a.w, z[4*j+3]);
            }
        }
    }
    const float nl = (float)((m + 1 < KWIN) ? (m + 1) : KWIN);
    float sm_ = 0.f, sq_ = 0.f;
    #pragma unroll
    for (int w = 0; w < VV; ++w) {
        z[w] = fmaf(nl, g_bA[c*VV + w], z[w]);
        sm_ += z[w];
        sq_  = fmaf(z[w], z[w], sq_);
    }
    #pragma unroll
    for (int off = 16; off > 0; off >>= 1) {
        sm_ += __shfl_xor_sync(0xFFFFFFFFu, sm_, off);
        sq_ += __shfl_xor_sync(0xFFFFFFFFu, sq_, off);
    }
    if (lane == 0) { red[wid] = sm_; red[16 + wid] = sq_; }
    __syncthreads();
    float ts = 0.f, tq = 0.f;
    #pragma unroll
    for (int i = 0; i < 8; ++i) { ts += red[pos*8 + i]; tq += red[16 + pos*8 + i]; }
    const float mean = ts * (1.f / 6400.f);
    const float var  = tq * (1.f / 6400.f) - mean*mean;
    const float rstd = rsqrtf(var + 1e-5f);

    const int ib = ((n*CIN + c)*LL + m)*VV;
    #pragma unroll
    for (int w = 0; w < VV; ++w) {
        float h = fmaf((z[w] - mean)*rstd, ln_gamma[c*VV + w], ln_beta[c*VV + w]);
        h = fmaxf(h, 0.f);
        out[ib + w] = fmaxf(h + x[ib + w], 0.f);
    }
}

// ---------------------------------------------------------------------------
extern "C" void kernel_launch(void* const* d_in, const int* in_sizes, int n_in,
                              void* d_out, int out_size) {
    const float* x      = (const float*)d_in[0];
    const float* A1     = (const float*)d_in[1];
    const float* A2     = (const float*)d_in[2];
    const float* A3     = (const float*)d_in[3];
    const float* conv_w = (const float*)d_in[4];
    const float* conv_b = (const float*)d_in[5];
    const float* gamma  = (const float*)d_in[6];
    const float* beta   = (const float*)d_in[7];
    const float* ei     = (const float*)d_in[8];
    float* out          = (float*)d_out;

    cudaFuncSetAttribute(gemm_kernel,
                         cudaFuncAttributeMaxDynamicSharedMemorySize, SM_TOTAL);

    prep_kernel<<<768, 256>>>(conv_w, A1, A2, A3, ei, conv_b);
    temporal_kernel<<<(NB*CIN*VV + 255) / 256, 256>>>(x);
    gemm_kernel<<<NB * (LL/2), 512, SM_TOTAL>>>(x, gamma, beta, out);
}

// round 11
// speedup vs baseline: 1.2222x; 1.2222x over previous
#include <cuda_runtime.h>
#include <cuda_fp16.h>
#include <cstdint>

// ---------------- problem shapes ----------------
#define NB    8
#define CIN   256
#define LL    1024
#define VV    25
#define PP    3
#define KWIN  9
#define APAD  28

// ---------------- gemm tiling -------------------
// CTA: 512 threads / 16 warps; 2 positions packed (cols = pos*25+v, 50 valid).
// M=768 (warp: 48 rows = 3 mtiles), N=56 (7 ntiles of 8), K=256 (16 ksteps).
// Single-pass fp16 (11-bit mantissa) -> 336 MMAs/warp.
#define MT    3
#define NT    7
#define KS    16
#define STR_ST 264              // sT row stride in fp16 elements
#define STR_Y  58               // Y row stride in floats (even: float2-safe; mod32=26)

// smem layout (bytes)
#define SM_STH   0              // s fp16: 56 rows x 264 (33 KB)
#define SM_Y     0              // union with sT (written after GEMM)
#define SM_AEFF  178176         // 768*58*4
#define SM_RED   186576
#define SM_TOTAL 186752

// ---------------- device scratch ----------------
__device__ float  g_s[NB*CIN*LL*VV];          // temporal sliding sums
__device__ __half g_Wf[48*KS*32*8];           // fragment-major W (fp16)
__device__ float  g_Aeff[PP*VV*APAD];         // A_p * ei, padded rows
__device__ float  g_bA[256*VV];               // folded bias

// ---------------------------------------------------------------------------
// prep: pack conv_w into m16n8k16 A-fragment layout (fp16);
// build Aeff (padded) and folded bias bA.
// ---------------------------------------------------------------------------
__global__ void prep_kernel(const float* __restrict__ conv_w,
                            const float* __restrict__ A1,
                            const float* __restrict__ A2,
                            const float* __restrict__ A3,
                            const float* __restrict__ ei,
                            const float* __restrict__ conv_b) {
    const int o = blockIdx.x;       // 0..767
    const int k = threadIdx.x;      // 0..255
    {
        float w = conv_w[o*CIN + k];
        const int mt  = o >> 4, r = o & 15;
        const int ks  = k >> 4, kk = k & 15;
        const int reg = ((r >> 3) & 1) | ((kk >> 3) << 1);   // a0..a3
        const int lane = (r & 7) * 4 + ((kk & 7) >> 1);
        const int byt  = kk & 1;
        const size_t off = ((((size_t)mt)*KS + ks)*32 + lane)*8 + reg*2 + byt;
        g_Wf[off] = __float2half(w);
    }
    if (blockIdx.x == 0) {
        for (int i = k; i < PP*VV*APAD; i += 256) {
            int p = i/(VV*APAD), rr = i%(VV*APAD), v = rr/APAD, w2 = rr%APAD;
            const float* Ap = (p==0) ? A1 : ((p==1) ? A2 : A3);
            g_Aeff[i] = (w2 < VV) ? Ap[v*VV + w2] * ei[p*VV*VV + v*VV + w2] : 0.f;
        }
    }
    if (blockIdx.x == 1) {
        const int c = k;
        for (int w2 = 0; w2 < VV; ++w2) {
            float acc = 0.f;
            for (int p = 0; p < PP; ++p) {
                const float* Ap = (p==0) ? A1 : ((p==1) ? A2 : A3);
                float cs = 0.f;
                for (int v = 0; v < VV; ++v)
                    cs += Ap[v*VV + w2] * ei[p*VV*VV + v*VV + w2];
                acc += conv_b[p*256 + c] * cs;
            }
            g_bA[c*VV + w2] = acc;
        }
    }
}

// ---------------------------------------------------------------------------
// temporal: causal 9-tap sliding sum over L.
// ---------------------------------------------------------------------------
__global__ void temporal_kernel(const float* __restrict__ x) {
    int t = blockIdx.x * blockDim.x + threadIdx.x;
    if (t >= NB*CIN*VV) return;
    int v  = t % VV;
    int rc = t / VV;
    int base = rc * (LL*VV) + v;
    float run = 0.f;
    #pragma unroll 4
    for (int m = 0; m < LL; ++m) {
        run += x[base + m*VV];
        if (m >= KWIN) run -= x[base + (m - KWIN)*VV];
        g_s[base + m*VV] = run;
    }
}

// ---------------------------------------------------------------------------
__device__ __forceinline__ void mma16816(float c[4], const uint32_t a[4],
                                         const uint32_t b[2]) {
    asm volatile(
        "mma.sync.aligned.m16n8k16.row.col.f32.f16.f16.f32 "
        "{%0,%1,%2,%3}, {%4,%5,%6,%7}, {%8,%9}, {%0,%1,%2,%3};"
        : "+f"(c[0]), "+f"(c[1]), "+f"(c[2]), "+f"(c[3])
        : "r"(a[0]), "r"(a[1]), "r"(a[2]), "r"(a[3]), "r"(b[0]), "r"(b[1]));
}

// ---------------------------------------------------------------------------
// fused mma.sync GEMM (fp16 single-pass) + spatial + LN + residual.
// One CTA = 2 positions; 512 threads.
// ---------------------------------------------------------------------------
__global__ __launch_bounds__(512, 1)
void gemm_kernel(const float* __restrict__ x,
                 const float* __restrict__ ln_gamma,
                 const float* __restrict__ ln_beta,
                 float* __restrict__ out) {
    extern __shared__ char smem[];
    __half* sth = (__half*)(smem + SM_STH);
    float*  Ysh = (float*)(smem + SM_Y);
    float*  Ae  = (float*)(smem + SM_AEFF);
    float*  red = (float*)(smem + SM_RED);

    const int t = threadIdx.x, wid = t >> 5, lane = t & 31;
    const int n  = blockIdx.x >> 9;
    const int m0 = (blockIdx.x & 511) * 2;

    // Aeff (separate region, persists through epilogue)
    for (int i = t; i < PP*VV*APAD; i += 512) Ae[i] = g_Aeff[i];

    // stage s -> fp16 transposed: thread = (ci, pos), 25 contiguous floats
    {
        const int ci = t & 255, posl = t >> 8;
        const float* srow = &g_s[((n*CIN + ci)*LL + (m0 + posl))*VV];
        #pragma unroll
        for (int v = 0; v < VV; ++v)
            sth[(posl*VV + v)*STR_ST + ci] = __float2half(srow[v]);
        // zero pad rows 50..55 (touched by nt=6)
        for (int i = t; i < 6*STR_ST; i += 512)
            sth[50*STR_ST + i] = __float2half(0.f);
    }
    __syncthreads();

    // -------------------- GEMM (single fp16 pass) --------------------
    float acc[MT][NT][4];
    #pragma unroll
    for (int mt = 0; mt < MT; ++mt)
        #pragma unroll
        for (int nt = 0; nt < NT; ++nt)
            #pragma unroll
            for (int r = 0; r < 4; ++r) acc[mt][nt][r] = 0.f;

    const uint4* __restrict__ Wf4 = (const uint4*)g_Wf;
    const int mbase = wid * MT;                  // warp's first mtile (0..45)
    const int brow  = (lane >> 2);
    const int bcol  = 2 * (lane & 3);

    uint4 A[MT];
    #pragma unroll
    for (int mt = 0; mt < MT; ++mt)
        A[mt] = Wf4[((size_t)(mbase + mt)*KS + 0)*32 + lane];

    for (int ks = 0; ks < KS; ++ks) {
        uint4 An[MT];
        if (ks < KS-1) {
            #pragma unroll
            for (int mt = 0; mt < MT; ++mt)
                An[mt] = Wf4[((size_t)(mbase + mt)*KS + ks + 1)*32 + lane];
        }
        #pragma unroll
        for (int nt = 0; nt < NT; ++nt) {
            const int o = (nt*8 + brow)*STR_ST + ks*16 + bcol;
            uint32_t b2[2];
            b2[0] = *(const uint32_t*)(sth + o);
            b2[1] = *(const uint32_t*)(sth + o + 8);
            #pragma unroll
            for (int mt = 0; mt < MT; ++mt)
                mma16816(acc[mt][nt], (const uint32_t*)&A[mt], b2);
        }
        if (ks < KS-1) {
            #pragma unroll
            for (int mt = 0; mt < MT; ++mt) A[mt] = An[mt];
        }
    }
    __syncthreads();   // sT dead; Y region reusable

    // -------------------- STS Y --------------------
    #pragma unroll
    for (int mt = 0; mt < MT; ++mt) {
        const int row0 = wid*48 + mt*16 + (lane >> 2);
        #pragma unroll
        for (int nt = 0; nt < NT; ++nt) {
            const int col = nt*8 + 2*(lane & 3);
            *(float2*)&Ysh[row0*STR_Y + col] =
                make_float2(acc[mt][nt][0], acc[mt][nt][1]);
            *(float2*)&Ysh[(row0+8)*STR_Y + col] =
                make_float2(acc[mt][nt][2], acc[mt][nt][3]);
        }
    }
    __syncthreads();

    // ---------- epilogue: spatial + LN + residual (both positions at once) ----
    const int pos = t >> 8;          // warps 0-7 -> pos 0, warps 8-15 -> pos 1
    const int c   = t & 255;
    const int m   = m0 + pos;

    float z[APAD];
    #pragma unroll
    for (int w = 0; w < APAD; ++w) z[w] = 0.f;

    #pragma unroll
    for (int p = 0; p < PP; ++p) {
        const float* yrow = &Ysh[(p*256 + c)*STR_Y + pos*VV];
        const float* arow = Ae + p*VV*APAD;
        #pragma unroll
        for (int v = 0; v < VV; ++v) {
            const float yv = yrow[v];
            const float4* a4 = (const float4*)(arow + v*APAD);
            #pragma unroll
            for (int j = 0; j < 7; ++j) {
                float4 a = a4[j];
                z[4*j+0] = fmaf(yv, a.x, z[4*j+0]);
                z[4*j+1] = fmaf(yv, a.y, z[4*j+1]);
                z[4*j+2] = fmaf(yv, a.z, z[4*j+2]);
                z[4*j+3] = fmaf(yv, a.w, z[4*j+3]);
            }
        }
    }
    const float nl = (float)((m + 1 < KWIN) ? (m + 1) : KWIN);
    float sm_ = 0.f, sq_ = 0.f;
    #pragma unroll
    for (int w = 0; w < VV; ++w) {
        z[w] = fmaf(nl, g_bA[c*VV + w], z[w]);
        sm_ += z[w];
        sq_  = fmaf(z[w], z[w], sq_);
    }
    #pragma unroll
    for (int off = 16; off > 0; off >>= 1) {
        sm_ += __shfl_xor_sync(0xFFFFFFFFu, sm_, off);
        sq_ += __shfl_xor_sync(0xFFFFFFFFu, sq_, off);
    }
    if (lane == 0) { red[wid] = sm_; red[16 + wid] = sq_; }
    __syncthreads();
    float ts = 0.f, tq = 0.f;
    #pragma unroll
    for (int i = 0; i < 8; ++i) { ts += red[pos*8 + i]; tq += red[16 + pos*8 + i]; }
    const float mean = ts * (1.f / 6400.f);
    const float var  = tq * (1.f / 6400.f) - mean*mean;
    const float rstd = rsqrtf(var + 1e-5f);

    const int ib = ((n*CIN + c)*LL + m)*VV;
    #pragma unroll
    for (int w = 0; w < VV; ++w) {
        float h = fmaf((z[w] - mean)*rstd, ln_gamma[c*VV + w], ln_beta[c*VV + w]);
        h = fmaxf(h, 0.f);
        out[ib + w] = fmaxf(h + x[ib + w], 0.f);
    }
}

// ---------------------------------------------------------------------------
extern "C" void kernel_launch(void* const* d_in, const int* in_sizes, int n_in,
                              void* d_out, int out_size) {
    const float* x      = (const float*)d_in[0];
    const float* A1     = (const float*)d_in[1];
    const float* A2     = (const float*)d_in[2];
    const float* A3     = (const float*)d_in[3];
    const float* conv_w = (const float*)d_in[4];
    const float* conv_b = (const float*)d_in[5];
    const float* gamma  = (const float*)d_in[6];
    const float* beta   = (const float*)d_in[7];
    const float* ei     = (const float*)d_in[8];
    float* out          = (float*)d_out;

    cudaFuncSetAttribute(gemm_kernel,
                         cudaFuncAttributeMaxDynamicSharedMemorySize, SM_TOTAL);

    prep_kernel<<<768, 256>>>(conv_w, A1, A2, A3, ei, conv_b);
    temporal_kernel<<<(NB*CIN*VV + 255) / 256, 256>>>(x);
    gemm_kernel<<<NB * (LL/2), 512, SM_TOTAL>>>(x, gamma, beta, out);
}

// round 12
// speedup vs baseline: 1.8252x; 1.4933x over previous
#include <cuda_runtime.h>
#include <cuda_fp16.h>
#include <cstdint>

// ---------------- problem shapes ----------------
#define NB    8
#define CIN   256
#define LL    1024
#define VV    25
#define PP    3
#define KWIN  9
#define APAD  28

// ---------------- gemm tiling -------------------
// CTA: 512 threads / 16 warps; 2 positions packed (cols = pos*25+v, 50 valid).
// M=768 (warp: 48 rows = 3 mtiles), N=56 (7 ntiles of 8), K=256 (16 ksteps).
#define MT    3
#define NT    7
#define KS    16
#define STR_ST 264              // sT row stride (fp16 elems): bank-safe for B-frag LDS
#define STR_Y  59               // Yp row stride (floats, odd: conflict-free col reads)

// ---------------- smem layout (bytes) -----------
// Region 0 is a union: sT (GEMM input) -> Yp (per-partition Y) -> z (output buf)
#define SM_ST    0              // 56*264*2  = 29568
#define SM_YP    0              // 256*59*4  = 60416
#define SM_Z     0              // 512*25*4  = 51200
#define SM_G     60416          // gamma 6400 floats
#define SM_B2    86016          // beta  6400 floats
#define SM_BA    111616         // bA    6400 floats
#define SM_AE    137216         // Aeff  3*25*28 floats = 8400
#define SM_RED   145616         // 32 floats
#define SM_TOTAL 145792

// ---------------- device scratch ----------------
__device__ float  g_s[NB*CIN*LL*VV];          // temporal sliding sums
__device__ __half g_Wf[48*KS*32*8];           // fragment-major W (fp16)
__device__ float  g_Aeff[PP*VV*APAD];         // A_p * ei, padded rows
__device__ float  g_bA[256*VV];               // folded bias

// ---------------------------------------------------------------------------
// prep: pack conv_w into m16n8k16 A-fragment layout (fp16);
// build Aeff (padded) and folded bias bA.
// ---------------------------------------------------------------------------
__global__ void prep_kernel(const float* __restrict__ conv_w,
                            const float* __restrict__ A1,
                            const float* __restrict__ A2,
                            const float* __restrict__ A3,
                            const float* __restrict__ ei,
                            const float* __restrict__ conv_b) {
    const int o = blockIdx.x;       // 0..767
    const int k = threadIdx.x;      // 0..255
    {
        float w = conv_w[o*CIN + k];
        const int mt  = o >> 4, r = o & 15;
        const int ks  = k >> 4, kk = k & 15;
        const int reg = ((r >> 3) & 1) | ((kk >> 3) << 1);   // a0..a3
        const int lane = (r & 7) * 4 + ((kk & 7) >> 1);
        const int byt  = kk & 1;
        const size_t off = ((((size_t)mt)*KS + ks)*32 + lane)*8 + reg*2 + byt;
        g_Wf[off] = __float2half(w);
    }
    if (blockIdx.x == 0) {
        for (int i = k; i < PP*VV*APAD; i += 256) {
            int p = i/(VV*APAD), rr = i%(VV*APAD), v = rr/APAD, w2 = rr%APAD;
            const float* Ap = (p==0) ? A1 : ((p==1) ? A2 : A3);
            g_Aeff[i] = (w2 < VV) ? Ap[v*VV + w2] * ei[p*VV*VV + v*VV + w2] : 0.f;
        }
    }
    if (blockIdx.x == 1) {
        const int c = k;
        for (int w2 = 0; w2 < VV; ++w2) {
            float acc = 0.f;
            for (int p = 0; p < PP; ++p) {
                const float* Ap = (p==0) ? A1 : ((p==1) ? A2 : A3);
                float cs = 0.f;
                for (int v = 0; v < VV; ++v)
                    cs += Ap[v*VV + w2] * ei[p*VV*VV + v*VV + w2];
                acc += conv_b[p*256 + c] * cs;
            }
            g_bA[c*VV + w2] = acc;
        }
    }
}

// ---------------------------------------------------------------------------
// temporal: causal 9-tap sliding sum over L, 4 segments per (n,ci,v).
// ---------------------------------------------------------------------------
#define NSEG 4
__global__ void temporal_kernel(const float* __restrict__ x) {
    int t = blockIdx.x * blockDim.x + threadIdx.x;
    if (t >= NB*CIN*VV*NSEG) return;
    const int v   = t % VV;
    const int seg = (t / VV) % NSEG;
    const int rc  = t / (VV*NSEG);               // n*CIN + ci
    const int base = rc * (LL*VV) + v;
    const int ms = seg * (LL/NSEG);
    const int me = ms + (LL/NSEG);

    float run = 0.f;
    #pragma unroll
    for (int l = (ms >= 8 ? ms - 8 : 0); l < ms; ++l)
        run += x[base + l*VV];
    for (int m = ms; m < me; ++m) {
        run += x[base + m*VV];
        g_s[base + m*VV] = run;
        if (m >= 8) run -= x[base + (m - 8)*VV];
    }
}

// ---------------------------------------------------------------------------
__device__ __forceinline__ void mma16816(float c[4], const uint32_t a[4],
                                         const uint32_t b[2]) {
    asm volatile(
        "mma.sync.aligned.m16n8k16.row.col.f32.f16.f16.f32 "
        "{%0,%1,%2,%3}, {%4,%5,%6,%7}, {%8,%9}, {%0,%1,%2,%3};"
        : "+f"(c[0]), "+f"(c[1]), "+f"(c[2]), "+f"(c[3])
        : "r"(a[0]), "r"(a[1]), "r"(a[2]), "r"(a[3]), "r"(b[0]), "r"(b[1]));
}

// ---------------------------------------------------------------------------
// fused fp16 GEMM + per-partition spatial + LN + residual; coalesced I/O.
// One CTA = 2 positions; 512 threads.
// ---------------------------------------------------------------------------
__global__ __launch_bounds__(512, 1)
void gemm_kernel(const float* __restrict__ x,
                 const float* __restrict__ ln_gamma,
                 const float* __restrict__ ln_beta,
                 float* __restrict__ out) {
    extern __shared__ char smem[];
    __half* sth = (__half*)(smem + SM_ST);
    float*  Yp  = (float*)(smem + SM_YP);
    float*  zs  = (float*)(smem + SM_Z);
    float*  Gs  = (float*)(smem + SM_G);
    float*  Bs  = (float*)(smem + SM_B2);
    float*  BAs = (float*)(smem + SM_BA);
    float*  Ae  = (float*)(smem + SM_AE);
    float*  red = (float*)(smem + SM_RED);

    const int t = threadIdx.x, wid = t >> 5, lane = t & 31;
    const int n  = blockIdx.x >> 9;
    const int m0 = (blockIdx.x & 511) * 2;

    // ---- coalesced const loads (per-(c,w) tables + Aeff) ----
    for (int i = t; i < 256*VV; i += 512) {
        Gs[i]  = ln_gamma[i];
        Bs[i]  = ln_beta[i];
        BAs[i] = g_bA[i];
    }
    for (int i = t; i < PP*VV*APAD; i += 512) Ae[i] = g_Aeff[i];

    // ---- stage s -> fp16 sT (coalesced reads; both positions contiguous) ----
    for (int idx = t; idx < 256*50; idx += 512) {
        const int ci = idx / 50, q = idx - ci*50;      // q = pos*25+v = sT row
        const float sv = g_s[(size_t)(n*CIN + ci)*(LL*VV) + m0*VV + q];
        sth[q*STR_ST + ci] = __float2half(sv);
    }
    for (int i = t; i < 6*STR_ST; i += 512)            // pad rows 50..55
        sth[50*STR_ST + i] = __float2half(0.f);
    __syncthreads();

    // -------------------- GEMM (single fp16 pass) --------------------
    float acc[MT][NT][4];
    #pragma unroll
    for (int mt = 0; mt < MT; ++mt)
        #pragma unroll
        for (int nt = 0; nt < NT; ++nt)
            #pragma unroll
            for (int r = 0; r < 4; ++r) acc[mt][nt][r] = 0.f;

    {
        const uint4* __restrict__ Wf4 = (const uint4*)g_Wf;
        const int mbase = wid * MT;
        const int brow  = (lane >> 2);
        const int bcol  = 2 * (lane & 3);

        uint4 A[MT];
        #pragma unroll
        for (int mt = 0; mt < MT; ++mt)
            A[mt] = Wf4[((size_t)(mbase + mt)*KS + 0)*32 + lane];

        for (int ks = 0; ks < KS; ++ks) {
            uint4 An[MT];
            if (ks < KS-1) {
                #pragma unroll
                for (int mt = 0; mt < MT; ++mt)
                    An[mt] = Wf4[((size_t)(mbase + mt)*KS + ks + 1)*32 + lane];
            }
            #pragma unroll
            for (int nt = 0; nt < NT; ++nt) {
                const int o = (nt*8 + brow)*STR_ST + ks*16 + bcol;
                uint32_t b2[2];
                b2[0] = *(const uint32_t*)(sth + o);
                b2[1] = *(const uint32_t*)(sth + o + 8);
                #pragma unroll
                for (int mt = 0; mt < MT; ++mt)
                    mma16816(acc[mt][nt], (const uint32_t*)&A[mt], b2);
            }
            if (ks < KS-1) {
                #pragma unroll
                for (int mt = 0; mt < MT; ++mt) A[mt] = An[mt];
            }
        }
    }
    __syncthreads();   // sT dead; region reused as Yp

    // ---- per-partition rounds: STS Y_p then accumulate spatial transform ----
    const int pos = t >> 8;
    const int c   = t & 255;
    const int m   = m0 + pos;

    float z[APAD];
    #pragma unroll
    for (int w = 0; w < APAD; ++w) z[w] = 0.f;

    for (int p = 0; p < PP; ++p) {
        if (p) __syncthreads();                        // prior round's reads done
        #pragma unroll
        for (int mt = 0; mt < MT; ++mt) {
            const int g = wid*MT + mt;                 // global 16-row tile id 0..47
            if ((g >> 4) == p) {
                const int lr  = (g & 15)*16 + (lane >> 2);
                #pragma unroll
                for (int nt = 0; nt < NT; ++nt) {
                    const int col = nt*8 + 2*(lane & 3);
                    Yp[lr*STR_Y + col]       = acc[mt][nt][0];
                    Yp[lr*STR_Y + col + 1]   = acc[mt][nt][1];
                    Yp[(lr+8)*STR_Y + col]   = acc[mt][nt][2];
                    Yp[(lr+8)*STR_Y + col+1] = acc[mt][nt][3];
                }
            }
        }
        __syncthreads();
        const float* yrow = &Yp[c*STR_Y + pos*VV];
        const float* arow = Ae + p*VV*APAD;
        #pragma unroll
        for (int v = 0; v < VV; ++v) {
            const float yv = yrow[v];
            const float4* a4 = (const float4*)(arow + v*APAD);
            #pragma unroll
            for (int j = 0; j < 7; ++j) {
                float4 a = a4[j];
                z[4*j+0] = fmaf(yv, a.x, z[4*j+0]);
                z[4*j+1] = fmaf(yv, a.y, z[4*j+1]);
                z[4*j+2] = fmaf(yv, a.z, z[4*j+2]);
                z[4*j+3] = fmaf(yv, a.w, z[4*j+3]);
            }
        }
    }

    // ---- bias + LN stats ----
    const float nl = (float)((m + 1 < KWIN) ? (m + 1) : KWIN);
    float sm_ = 0.f, sq_ = 0.f;
    #pragma unroll
    for (int w = 0; w < VV; ++w) {
        z[w] = fmaf(nl, BAs[c*VV + w], z[w]);
        sm_ += z[w];
        sq_  = fmaf(z[w], z[w], sq_);
    }
    #pragma unroll
    for (int off = 16; off > 0; off >>= 1) {
        sm_ += __shfl_xor_sync(0xFFFFFFFFu, sm_, off);
        sq_ += __shfl_xor_sync(0xFFFFFFFFu, sq_, off);
    }
    if (lane == 0) { red[wid] = sm_; red[16 + wid] = sq_; }
    __syncthreads();                                   // also guards Yp -> zs reuse
    float ts = 0.f, tq = 0.f;
    #pragma unroll
    for (int i = 0; i < 8; ++i) { ts += red[pos*8 + i]; tq += red[16 + pos*8 + i]; }
    const float mean = ts * (1.f / 6400.f);
    const float var  = tq * (1.f / 6400.f) - mean*mean;
    const float rstd = rsqrtf(var + 1e-5f);

    // ---- LN + relu -> z-buffer (smem), layout zs[c*50 + pos*25 + w] ----
    #pragma unroll
    for (int w = 0; w < VV; ++w) {
        float h = fmaf((z[w] - mean)*rstd, Gs[c*VV + w], Bs[c*VV + w]);
        zs[c*50 + pos*VV + w] = fmaxf(h, 0.f);
    }
    __syncthreads();

    // ---- coalesced residual + store (both positions contiguous per c) ----
    for (int idx = t; idx < 256*50; idx += 512) {
        const int c2 = idx / 50, q = idx - c2*50;
        const size_t a = (size_t)(n*CIN + c2)*(LL*VV) + m0*VV + q;
        out[a] = fmaxf(zs[idx] + x[a], 0.f);
    }
}

// ---------------------------------------------------------------------------
extern "C" void kernel_launch(void* const* d_in, const int* in_sizes, int n_in,
                              void* d_out, int out_size) {
    const float* x      = (const float*)d_in[0];
    const float* A1     = (const float*)d_in[1];
    const float* A2     = (const float*)d_in[2];
    const float* A3     = (const float*)d_in[3];
    const float* conv_w = (const float*)d_in[4];
    const float* conv_b = (const float*)d_in[5];
    const float* gamma  = (const float*)d_in[6];
    const float* beta   = (const float*)d_in[7];
    const float* ei     = (const float*)d_in[8];
    float* out          = (float*)d_out;

    cudaFuncSetAttribute(gemm_kernel,
                         cudaFuncAttributeMaxDynamicSharedMemorySize, SM_TOTAL);

    prep_kernel<<<768, 256>>>(conv_w, A1, A2, A3, ei, conv_b);
    temporal_kernel<<<(NB*CIN*VV*NSEG + 255) / 256, 256>>>(x);
    gemm_kernel<<<NB * (LL/2), 512, SM_TOTAL>>>(x, gamma, beta, out);
}

// round 13
// speedup vs baseline: 2.3450x; 1.2848x over previous
#include <cuda_runtime.h>
#include <cuda_fp16.h>
#include <cstdint>

// ---------------- problem shapes ----------------
#define NB    8
#define CIN   256
#define LL    1024
#define VV    25
#define PP    3
#define KWIN  9
#define APAD  28

// ---------------- gemm-1 tiling -------------------
// CTA: 512 threads / 16 warps; 2 positions packed (cols = pos*25+v, 50 valid).
// M=768 (warp: 48 rows = 3 mtiles), N=56 (7 ntiles), K=256 (16 ksteps).
#define MT    3
#define NT    7
#define KS    16
#define STR_ST 264              // sT row stride (fp16)
// ---------------- gemm-2 (spatial) ---------------
// M=512 (pos,c), K=80 (p*25+v, pad 75..79 = 0), N=32 (w, 25 valid).
#define STR_YH 88               // Yh row stride (fp16)
#define KS2   5

// ---------------- smem layout (bytes) -----------
// union region: sT (29568) -> Yh (90112) -> zs (51200)
#define SM_ST    0
#define SM_YH    0
#define SM_Z     0
#define SM_G     90112          // gamma 6400 f32
#define SM_B2T   115712         // beta  6400 f32
#define SM_BA    141312         // bA    6400 f32
#define SM_B2H   166912         // Acat fp16 32x88
#define SM_RED   172544
#define SM_TOTAL 172672

// ---------------- device scratch ----------------
__device__ float  g_s[NB*CIN*LL*VV];          // temporal sliding sums
__device__ __half g_Wf[48*KS*32*8];           // fragment-major W (fp16)
__device__ float  g_bA[256*VV];               // folded bias
__device__ __half g_B2h[32*STR_YH];           // Acat[(w)][(p*25+v)] fp16, padded zeros

// ---------------------------------------------------------------------------
// prep: W -> fp16 A-fragment layout; Acat fp16 table; folded bias bA.
// ---------------------------------------------------------------------------
__global__ void prep_kernel(const float* __restrict__ conv_w,
                            const float* __restrict__ A1,
                            const float* __restrict__ A2,
                            const float* __restrict__ A3,
                            const float* __restrict__ ei,
                            const float* __restrict__ conv_b) {
    const int o = blockIdx.x;       // 0..767
    const int k = threadIdx.x;      // 0..255
    {
        float w = conv_w[o*CIN + k];
        const int mt  = o >> 4, r = o & 15;
        const int ks  = k >> 4, kk = k & 15;
        const int reg = ((r >> 3) & 1) | ((kk >> 3) << 1);   // a0..a3
        const int lane = (r & 7) * 4 + ((kk & 7) >> 1);
        const int byt  = kk & 1;
        const size_t off = ((((size_t)mt)*KS + ks)*32 + lane)*8 + reg*2 + byt;
        g_Wf[off] = __float2half(w);
    }
    if (blockIdx.x == 0) {
        // Acat[w][p*25+v] = A_p[v][w] * ei[p][v][w]; zero outside valid range
        for (int i = k; i < 32*STR_YH; i += 256) {
            const int w2 = i / STR_YH, pv = i % STR_YH;
            float val = 0.f;
            if (w2 < VV && pv < PP*VV) {
                const int p = pv / VV, v = pv % VV;
                const float* Ap = (p==0) ? A1 : ((p==1) ? A2 : A3);
                val = Ap[v*VV + w2] * ei[p*VV*VV + v*VV + w2];
            }
            g_B2h[i] = __float2half(val);
        }
    }
    if (blockIdx.x == 1) {
        const int c = k;
        for (int w2 = 0; w2 < VV; ++w2) {
            float acc = 0.f;
            for (int p = 0; p < PP; ++p) {
                const float* Ap = (p==0) ? A1 : ((p==1) ? A2 : A3);
                float cs = 0.f;
                for (int v = 0; v < VV; ++v)
                    cs += Ap[v*VV + w2] * ei[p*VV*VV + v*VV + w2];
                acc += conv_b[p*256 + c] * cs;
            }
            g_bA[c*VV + w2] = acc;
        }
    }
}

// ---------------------------------------------------------------------------
// temporal: causal 9-tap sliding sum over L, 4 segments per (n,ci,v).
// ---------------------------------------------------------------------------
#define NSEG 4
__global__ void temporal_kernel(const float* __restrict__ x) {
    int t = blockIdx.x * blockDim.x + threadIdx.x;
    if (t >= NB*CIN*VV*NSEG) return;
    const int v   = t % VV;
    const int seg = (t / VV) % NSEG;
    const int rc  = t / (VV*NSEG);
    const int base = rc * (LL*VV) + v;
    const int ms = seg * (LL/NSEG);
    const int me = ms + (LL/NSEG);

    float run = 0.f;
    #pragma unroll
    for (int l = (ms >= 8 ? ms - 8 : 0); l < ms; ++l)
        run += x[base + l*VV];
    for (int m = ms; m < me; ++m) {
        run += x[base + m*VV];
        g_s[base + m*VV] = run;
        if (m >= 8) run -= x[base + (m - 8)*VV];
    }
}

// ---------------------------------------------------------------------------
__device__ __forceinline__ void mma16816(float c[4], const uint32_t a[4],
                                         const uint32_t b[2]) {
    asm volatile(
        "mma.sync.aligned.m16n8k16.row.col.f32.f16.f16.f32 "
        "{%0,%1,%2,%3}, {%4,%5,%6,%7}, {%8,%9}, {%0,%1,%2,%3};"
        : "+f"(c[0]), "+f"(c[1]), "+f"(c[2]), "+f"(c[3])
        : "r"(a[0]), "r"(a[1]), "r"(a[2]), "r"(a[3]), "r"(b[0]), "r"(b[1]));
}

// ---------------------------------------------------------------------------
// fused: fp16 GEMM-1 (channels) + fp16 GEMM-2 (spatial) + LN + residual.
// One CTA = 2 positions; 512 threads.
// ---------------------------------------------------------------------------
__global__ __launch_bounds__(512, 1)
void gemm_kernel(const float* __restrict__ x,
                 const float* __restrict__ ln_gamma,
                 const float* __restrict__ ln_beta,
                 float* __restrict__ out) {
    extern __shared__ char smem[];
    __half* sth = (__half*)(smem + SM_ST);
    __half* Yh  = (__half*)(smem + SM_YH);
    float*  zs  = (float*)(smem + SM_Z);
    float*  Gs  = (float*)(smem + SM_G);
    float*  Bs  = (float*)(smem + SM_B2T);
    float*  BAs = (float*)(smem + SM_BA);
    __half* B2h = (__half*)(smem + SM_B2H);
    float*  red = (float*)(smem + SM_RED);

    const int t = threadIdx.x, wid = t >> 5, lane = t & 31;
    const int n  = blockIdx.x >> 9;
    const int m0 = (blockIdx.x & 511) * 2;

    // ---- coalesced const loads ----
    for (int i = t; i < 256*VV; i += 512) {
        Gs[i]  = ln_gamma[i];
        Bs[i]  = ln_beta[i];
        BAs[i] = g_bA[i];
    }
    for (int i = t; i < (32*STR_YH)/2; i += 512)
        ((uint32_t*)B2h)[i] = ((const uint32_t*)g_B2h)[i];

    // ---- stage s -> fp16 sT (coalesced; both positions contiguous) ----
    for (int idx = t; idx < 256*50; idx += 512) {
        const int ci = idx / 50, q = idx - ci*50;      // q = pos*25+v
        const float sv = g_s[(size_t)(n*CIN + ci)*(LL*VV) + m0*VV + q];
        sth[q*STR_ST + ci] = __float2half(sv);
    }
    for (int i = t; i < 6*STR_ST; i += 512)            // pad rows 50..55
        sth[50*STR_ST + i] = __float2half(0.f);
    __syncthreads();

    // -------------------- GEMM-1 (channels, fp16) --------------------
    float acc[MT][NT][4];
    #pragma unroll
    for (int mt = 0; mt < MT; ++mt)
        #pragma unroll
        for (int nt = 0; nt < NT; ++nt)
            #pragma unroll
            for (int r = 0; r < 4; ++r) acc[mt][nt][r] = 0.f;

    {
        const uint4* __restrict__ Wf4 = (const uint4*)g_Wf;
        const int mbase = wid * MT;
        const int brow  = (lane >> 2);
        const int bcol  = 2 * (lane & 3);

        uint4 A[MT];
        #pragma unroll
        for (int mt = 0; mt < MT; ++mt)
            A[mt] = Wf4[((size_t)(mbase + mt)*KS + 0)*32 + lane];

        for (int ks = 0; ks < KS; ++ks) {
            uint4 An[MT];
            if (ks < KS-1) {
                #pragma unroll
                for (int mt = 0; mt < MT; ++mt)
                    An[mt] = Wf4[((size_t)(mbase + mt)*KS + ks + 1)*32 + lane];
            }
            #pragma unroll
            for (int nt = 0; nt < NT; ++nt) {
                const int o = (nt*8 + brow)*STR_ST + ks*16 + bcol;
                uint32_t b2[2];
                b2[0] = *(const uint32_t*)(sth + o);
                b2[1] = *(const uint32_t*)(sth + o + 8);
                #pragma unroll
                for (int mt = 0; mt < MT; ++mt)
                    mma16816(acc[mt][nt], (const uint32_t*)&A[mt], b2);
            }
            if (ks < KS-1) {
                #pragma unroll
                for (int mt = 0; mt < MT; ++mt) A[mt] = An[mt];
            }
        }
    }
    __syncthreads();   // sT dead; region reused as Yh

    // ---- scatter Y -> Yh[(pos*256+c)][p*25+v] (fp16); zero K-pad cols ----
    {
        #pragma unroll
        for (int j = 75; j < 80; ++j)                  // one row per thread
            Yh[t*STR_YH + j] = __float2half(0.f);

        #pragma unroll
        for (int mt = 0; mt < MT; ++mt) {
            const int row = wid*48 + mt*16 + (lane >> 2);   // p*256 + c (rows <8)
            const int p  = row >> 8;
            const int c  = row & 255;
            #pragma unroll
            for (int nt = 0; nt < NT; ++nt) {
                #pragma unroll
                for (int j = 0; j < 2; ++j) {
                    const int col = nt*8 + 2*(lane & 3) + j;
                    if (col < 50) {
                        const int pos = (col >= VV);
                        const int v   = col - pos*VV;
                        const int dst = (pos*256 + c)*STR_YH + p*VV + v;
                        Yh[dst]              = __float2half(acc[mt][nt][j]);
                        Yh[dst + 8*STR_YH]   = __float2half(acc[mt][nt][2+j]); // row+8
                    }
                }
            }
        }
    }
    __syncthreads();

    // -------------------- GEMM-2 (spatial, fp16) --------------------
    // M=512: warp wid owns mtiles wid*2, wid*2+1 (rows wid*32..wid*32+31)
    float acc2[2][4][4];
    #pragma unroll
    for (int mt = 0; mt < 2; ++mt)
        #pragma unroll
        for (int nt = 0; nt < 4; ++nt)
            #pragma unroll
            for (int r = 0; r < 4; ++r) acc2[mt][nt][r] = 0.f;

    {
        const int brow = (lane >> 2);
        const int bcol = 2 * (lane & 3);
        for (int ks2 = 0; ks2 < KS2; ++ks2) {
            uint32_t bf[4][2];
            #pragma unroll
            for (int nt = 0; nt < 4; ++nt) {
                const int o = (nt*8 + brow)*STR_YH + ks2*16 + bcol;
                bf[nt][0] = *(const uint32_t*)(B2h + o);
                bf[nt][1] = *(const uint32_t*)(B2h + o + 8);
            }
            #pragma unroll
            for (int mt = 0; mt < 2; ++mt) {
                const int row0 = (wid*2 + mt)*16 + brow;
                const int base = row0*STR_YH + ks2*16 + bcol;
                uint32_t a[4];
                a[0] = *(const uint32_t*)(Yh + base);
                a[1] = *(const uint32_t*)(Yh + base + 8*STR_YH);
                a[2] = *(const uint32_t*)(Yh + base + 8);
                a[3] = *(const uint32_t*)(Yh + base + 8*STR_YH + 8);
                #pragma unroll
                for (int nt = 0; nt < 4; ++nt)
                    mma16816(acc2[mt][nt], a, bf[nt]);
            }
        }
    }

    // ---- bias + LN stats on fragments (warp's rows all in one position) ----
    const int pos = wid >> 3;
    const int m   = m0 + pos;
    const float nl = (float)((m + 1 < KWIN) ? (m + 1) : KWIN);

    float sm_ = 0.f, sq_ = 0.f;
    #pragma unroll
    for (int mt = 0; mt < 2; ++mt) {
        #pragma unroll
        for (int r2 = 0; r2 < 2; ++r2) {               // r>>1: row vs row+8
            const int c = ((wid*2 + mt)*16 + (lane >> 2) + 8*r2) & 255;
            #pragma unroll
            for (int nt = 0; nt < 4; ++nt) {
                #pragma unroll
                for (int j = 0; j < 2; ++j) {
                    const int w = nt*8 + 2*(lane & 3) + j;
                    if (w < VV) {
                        float zv = acc2[mt][nt][r2*2 + j] + nl*BAs[c*VV + w];
                        acc2[mt][nt][r2*2 + j] = zv;
                        sm_ += zv;
                        sq_  = fmaf(zv, zv, sq_);
                    }
                }
            }
        }
    }
    #pragma unroll
    for (int off = 16; off > 0; off >>= 1) {
        sm_ += __shfl_xor_sync(0xFFFFFFFFu, sm_, off);
        sq_ += __shfl_xor_sync(0xFFFFFFFFu, sq_, off);
    }
    if (lane == 0) { red[wid] = sm_; red[16 + wid] = sq_; }
    __syncthreads();
    float ts = 0.f, tq = 0.f;
    #pragma unroll
    for (int i = 0; i < 8; ++i) { ts += red[pos*8 + i]; tq += red[16 + pos*8 + i]; }
    const float mean = ts * (1.f / 6400.f);
    const float var  = tq * (1.f / 6400.f) - mean*mean;
    const float rstd = rsqrtf(var + 1e-5f);

    // ---- LN + relu -> zs[c*50 + pos*25 + w] ----
    #pragma unroll
    for (int mt = 0; mt < 2; ++mt) {
        #pragma unroll
        for (int r2 = 0; r2 < 2; ++r2) {
            const int c = ((wid*2 + mt)*16 + (lane >> 2) + 8*r2) & 255;
            #pragma unroll
            for (int nt = 0; nt < 4; ++nt) {
                #pragma unroll
                for (int j = 0; j < 2; ++j) {
                    const int w = nt*8 + 2*(lane & 3) + j;
                    if (w < VV) {
                        const float zv = acc2[mt][nt][r2*2 + j];
                        float h = fmaf((zv - mean)*rstd, Gs[c*VV + w], Bs[c*VV + w]);
                        zs[c*50 + pos*VV + w] = fmaxf(h, 0.f);
                    }
                }
            }
        }
    }
    __syncthreads();

    // ---- coalesced residual + store ----
    for (int idx = t; idx < 256*50; idx += 512) {
        const int c2 = idx / 50, q = idx - c2*50;
        const size_t a = (size_t)(n*CIN + c2)*(LL*VV) + m0*VV + q;
        out[a] = fmaxf(zs[idx] + x[a], 0.f);
    }
}

// ---------------------------------------------------------------------------
extern "C" void kernel_launch(void* const* d_in, const int* in_sizes, int n_in,
                              void* d_out, int out_size) {
    const float* x      = (const float*)d_in[0];
    const float* A1     = (const float*)d_in[1];
    const float* A2     = (const float*)d_in[2];
    const float* A3     = (const float*)d_in[3];
    const float* conv_w = (const float*)d_in[4];
    const float* conv_b = (const float*)d_in[5];
    const float* gamma  = (const float*)d_in[6];
    const float* beta   = (const float*)d_in[7];
    const float* ei     = (const float*)d_in[8];
    float* out          = (float*)d_out;

    cudaFuncSetAttribute(gemm_kernel,
                         cudaFuncAttributeMaxDynamicSharedMemorySize, SM_TOTAL);

    prep_kernel<<<768, 256>>>(conv_w, A1, A2, A3, ei, conv_b);
    temporal_kernel<<<(NB*CIN*VV*NSEG + 255) / 256, 256>>>(x);
    gemm_kernel<<<NB * (LL/2), 512, SM_TOTAL>>>(x, gamma, beta, out);
}